// round 15
// baseline (speedup 1.0000x reference)
#include <cuda_runtime.h>

#define TSTEPS  1000
#define BATCH   256
#define INDIM   3
#define HID     512
#define OUTD    2
#define BETA    0.8f
#define THRESH  1.0f

#define NCHUNK  25
#define CHLEN   (TSTEPS / NCHUNK)    // 40
#define WARMK   50                   // 0.8^50 ~ 1.4e-5 truncation (validated safe)
#define XSMAX   ((WARMK + CHLEN) * INDIM)

// ---------------------------------------------------------------------------
// Time-parallel fused SNN kernel. Body identical to the proven 79.9us kernel
// (scalar xs reads, __stcs streaming stores, 56-reg codegen pinned).
// Change vs R14: NCHUNK 20 -> 25 (6400 write streams), riding the measured
// streams->bandwidth gradient while issue (+13% work -> ~76%) stays sub-ceiling.
// Grid (BATCH, NCHUNK), 128 threads x 4 hidden units per block.
// ---------------------------------------------------------------------------
__global__ __launch_bounds__(128, 9) void snn_fused_kernel(
    const float* __restrict__ x,    // [T, B, IN]
    const float* __restrict__ W1,   // [H, IN]
    const float* __restrict__ W2,   // [OUT, H]
    float* __restrict__ spk,        // [T, B, H]
    float* __restrict__ avg)        // [B, OUT]
{
    __shared__ float xs[XSMAX];
    __shared__ float red0[10], red1[10], sig0[10], sig1[10];

    const int b     = blockIdx.x;
    const int chunk = blockIdx.y;
    const bool last = (chunk == NCHUNK - 1);
    const int tid   = threadIdx.x;         // 0..127
    const int lane  = tid & 31;
    const int h0    = tid * 4;

    const int start  = chunk * CHLEN;
    const int nwarm  = (chunk == 0) ? 0 : WARMK;
    const int wstart = start - nwarm;
    const int nsteps = nwarm + CHLEN;

    if (last && tid < 10) { red0[tid] = 0.f; red1[tid] = 0.f; }

    // --- stage x[wstart .. start+CHLEN) for this batch into shared ---
    for (int i = tid; i < nsteps; i += 128) {
        const float* src = x + ((size_t)(wstart + i) * BATCH + b) * INDIM;
        xs[i * 3 + 0] = __ldg(src + 0);
        xs[i * 3 + 1] = __ldg(src + 1);
        xs[i * 3 + 2] = __ldg(src + 2);
    }

    // --- W1 rows + W2 columns for our 4 hidden units ---
    float w[4][3], w2a[4], w2b[4];
#pragma unroll
    for (int j = 0; j < 4; ++j) {
#pragma unroll
        for (int i = 0; i < 3; ++i)
            w[j][i] = __ldg(&W1[(h0 + j) * INDIM + i]);
        w2a[j] = __ldg(&W2[h0 + j]);
        w2b[j] = __ldg(&W2[HID + h0 + j]);
    }

    __syncthreads();

    float m0 = 0.f, m1 = 0.f, m2 = 0.f, m3 = 0.f;

    // ---------------- warm-up (no stores) ----------------
#pragma unroll 4
    for (int i = 0; i < nwarm; ++i) {
        const float x0 = xs[i * 3 + 0];
        const float x1 = xs[i * 3 + 1];
        const float x2 = xs[i * 3 + 2];
        {
            float cur = fmaf(x0, w[0][0], fmaf(x1, w[0][1], x2 * w[0][2]));
            m0 = (m0 > THRESH) ? 0.0f : fmaf(BETA, m0, cur);
        }
        {
            float cur = fmaf(x0, w[1][0], fmaf(x1, w[1][1], x2 * w[1][2]));
            m1 = (m1 > THRESH) ? 0.0f : fmaf(BETA, m1, cur);
        }
        {
            float cur = fmaf(x0, w[2][0], fmaf(x1, w[2][1], x2 * w[2][2]));
            m2 = (m2 > THRESH) ? 0.0f : fmaf(BETA, m2, cur);
        }
        {
            float cur = fmaf(x0, w[3][0], fmaf(x1, w[3][1], x2 * w[3][2]));
            m3 = (m3 > THRESH) ? 0.0f : fmaf(BETA, m3, cur);
        }
    }

    float4* out = reinterpret_cast<float4*>(spk + ((size_t)start * BATCH + b) * HID + h0);
    const size_t t_stride4 = (size_t)BATCH * HID / 4;

    // ---------------- stored steps ----------------
    const int nmain = last ? (CHLEN - 10) : CHLEN;   // 30 or 40
#pragma unroll 4
    for (int i = 0; i < nmain; ++i) {
        const int k = nwarm + i;
        const float x0 = xs[k * 3 + 0];
        const float x1 = xs[k * 3 + 1];
        const float x2 = xs[k * 3 + 2];

        float4 s;
        {
            float cur = fmaf(x0, w[0][0], fmaf(x1, w[0][1], x2 * w[0][2]));
            m0  = (m0 > THRESH) ? 0.0f : fmaf(BETA, m0, cur);
            s.x = (m0 > THRESH) ? 1.0f : 0.0f;
        }
        {
            float cur = fmaf(x0, w[1][0], fmaf(x1, w[1][1], x2 * w[1][2]));
            m1  = (m1 > THRESH) ? 0.0f : fmaf(BETA, m1, cur);
            s.y = (m1 > THRESH) ? 1.0f : 0.0f;
        }
        {
            float cur = fmaf(x0, w[2][0], fmaf(x1, w[2][1], x2 * w[2][2]));
            m2  = (m2 > THRESH) ? 0.0f : fmaf(BETA, m2, cur);
            s.z = (m2 > THRESH) ? 1.0f : 0.0f;
        }
        {
            float cur = fmaf(x0, w[3][0], fmaf(x1, w[3][1], x2 * w[3][2]));
            m3  = (m3 > THRESH) ? 0.0f : fmaf(BETA, m3, cur);
            s.w = (m3 > THRESH) ? 1.0f : 0.0f;
        }
        __stcs(&out[(size_t)i * t_stride4], s);
    }

    // ---------------- last chunk: final 10 steps + readout ----------------
    if (last) {
        float q0[10], q1[10];
#pragma unroll
        for (int tt = 0; tt < 10; ++tt) {
            const int k = nwarm + (CHLEN - 10) + tt;
            const float x0 = xs[k * 3 + 0];
            const float x1 = xs[k * 3 + 1];
            const float x2 = xs[k * 3 + 2];

            float4 s;
            {
                float cur = fmaf(x0, w[0][0], fmaf(x1, w[0][1], x2 * w[0][2]));
                m0  = (m0 > THRESH) ? 0.0f : fmaf(BETA, m0, cur);
                s.x = (m0 > THRESH) ? 1.0f : 0.0f;
            }
            {
                float cur = fmaf(x0, w[1][0], fmaf(x1, w[1][1], x2 * w[1][2]));
                m1  = (m1 > THRESH) ? 0.0f : fmaf(BETA, m1, cur);
                s.y = (m1 > THRESH) ? 1.0f : 0.0f;
            }
            {
                float cur = fmaf(x0, w[2][0], fmaf(x1, w[2][1], x2 * w[2][2]));
                m2  = (m2 > THRESH) ? 0.0f : fmaf(BETA, m2, cur);
                s.z = (m2 > THRESH) ? 1.0f : 0.0f;
            }
            {
                float cur = fmaf(x0, w[3][0], fmaf(x1, w[3][1], x2 * w[3][2]));
                m3  = (m3 > THRESH) ? 0.0f : fmaf(BETA, m3, cur);
                s.w = (m3 > THRESH) ? 1.0f : 0.0f;
            }
            __stcs(&out[(size_t)(CHLEN - 10 + tt) * t_stride4], s);

            q0[tt] = fmaf(s.x, w2a[0], fmaf(s.y, w2a[1], fmaf(s.z, w2a[2], s.w * w2a[3])));
            q1[tt] = fmaf(s.x, w2b[0], fmaf(s.y, w2b[1], fmaf(s.z, w2b[2], s.w * w2b[3])));
        }

#pragma unroll
        for (int tt = 0; tt < 10; ++tt) {
            float p0 = q0[tt], p1 = q1[tt];
#pragma unroll
            for (int off = 16; off > 0; off >>= 1) {
                p0 += __shfl_down_sync(0xffffffffu, p0, off);
                p1 += __shfl_down_sync(0xffffffffu, p1, off);
            }
            if (lane == 0) {
                atomicAdd(&red0[tt], p0);
                atomicAdd(&red1[tt], p1);
            }
        }
        __syncthreads();

        if (tid < 10) {
            sig0[tid] = 1.0f / (1.0f + expf(-red0[tid]));
            sig1[tid] = 1.0f / (1.0f + expf(-red1[tid]));
        }
        __syncthreads();

        if (tid == 0) {
            float a0 = 0.f, a1 = 0.f;
#pragma unroll
            for (int i = 0; i < 10; ++i) { a0 += sig0[i]; a1 += sig1[i]; }
            avg[b * OUTD + 0] = a0 * 0.1f;
            avg[b * OUTD + 1] = a1 * 0.1f;
        }
    }
}

// ---------------------------------------------------------------------------
extern "C" void kernel_launch(void* const* d_in, const int* in_sizes, int n_in,
                              void* d_out, int out_size) {
    const float* x_seq = (const float*)d_in[0];  // [T, B, IN]
    const float* W1    = (const float*)d_in[1];  // [H, IN]
    const float* W2    = (const float*)d_in[2];  // [OUT, H]

    float* out = (float*)d_out;
    float* spk = out;                                     // [T, B, H]
    float* avg = out + ((size_t)out_size - BATCH * OUTD); // [B, OUT] tail

    dim3 grid(BATCH, NCHUNK);
    snn_fused_kernel<<<grid, 128>>>(x_seq, W1, W2, spk, avg);
}